// round 16
// baseline (speedup 1.0000x reference)
#include <cuda_runtime.h>
#include <cuda_fp16.h>
#include <math.h>

// Decoder free-run greedy decode. B=1024, T=64, V=256, LAT=256, H=512, L=2.
// R16: fp16 m16n8k16 2-term split GEMMs, ldmatrix + cp.async double-buffer,
// 512-thread blocks (16 warps, warp tile 16x24) for 2x latency hiding.
// MMA order per accumulator identical to R15 (rel_err = 0 validated).
// pre_kernel keeps the proven tf32 route (runs once). Multi-launch,
// graph-capturable. __device__ symbols referenced from device code only.

#define Bq   1024
#define Hq   512
#define TH3  1536
#define Vq   256
#define LATq 256
#define Tq   64
#define SP   20      // tf32 pre-kernel smem pitch

// ---------------- device scratch ------------------------------------------
__device__ float g_pre[Bq * TH3];
__device__ float g_wvT[Vq * TH3];          // w_ih0 vocab cols [v][gate3H]
__device__ float g_wfcT[Hq * Vq];          // w_fc transposed [k][v]
__device__ float g_h0f[2][Bq * Hq], g_h1f[2][Bq * Hq];
__device__ int   g_idx[Bq];
// fp16 2-term splits: weights [mat: 0=whh0 1=wih1 2=whh1][term]
__device__ __align__(16) __half g_w16[3][2][TH3 * Hq];
__device__ __align__(16) __half g_h0t[2][2][Bq * Hq];   // [parity][term]
__device__ __align__(16) __half g_h1t[2][2][Bq * Hq];
// tf32 split data for pre_kernel
__device__ float g_wah[TH3 * LATq], g_wal[TH3 * LATq];
__device__ float g_lath[Bq * LATq], g_latl[Bq * LATq];

__device__ __forceinline__ float sigmoidf_(float x) {
    return 1.0f / (1.0f + expf(-x));
}
__device__ __forceinline__ unsigned cvt_tf32(float x) {
    unsigned r;
    asm("cvt.rna.tf32.f32 %0, %1;" : "=r"(r) : "f"(x));
    return r;
}
__device__ __forceinline__ void split1(float x, float &h, float &l) {
    float hf = __uint_as_float(cvt_tf32(x));
    h = hf;
    l = __uint_as_float(cvt_tf32(x - hf));
}
__device__ __forceinline__ void split2h(float x, __half &a, __half &b) {
    a = __float2half_rn(x);
    b = __float2half_rn(x - __half2float(a));
}
__device__ __forceinline__ void mma_tf32(float c[4], const unsigned a[4],
                                         unsigned b0, unsigned b1) {
    asm volatile(
        "mma.sync.aligned.m16n8k8.row.col.f32.tf32.tf32.f32 "
        "{%0,%1,%2,%3}, {%4,%5,%6,%7}, {%8,%9}, {%0,%1,%2,%3};"
        : "+f"(c[0]), "+f"(c[1]), "+f"(c[2]), "+f"(c[3])
        : "r"(a[0]), "r"(a[1]), "r"(a[2]), "r"(a[3]), "r"(b0), "r"(b1));
}
__device__ __forceinline__ void mma_f16(float c[4], const unsigned a[4],
                                        unsigned b0, unsigned b1) {
    asm volatile(
        "mma.sync.aligned.m16n8k16.row.col.f32.f16.f16.f32 "
        "{%0,%1,%2,%3}, {%4,%5,%6,%7}, {%8,%9}, {%0,%1,%2,%3};"
        : "+f"(c[0]), "+f"(c[1]), "+f"(c[2]), "+f"(c[3])
        : "r"(a[0]), "r"(a[1]), "r"(a[2]), "r"(a[3]), "r"(b0), "r"(b1));
}
__device__ __forceinline__ void ldsm_x4(unsigned r[4], unsigned addr) {
    asm volatile(
        "ldmatrix.sync.aligned.m8n8.x4.shared.b16 {%0,%1,%2,%3}, [%4];"
        : "=r"(r[0]), "=r"(r[1]), "=r"(r[2]), "=r"(r[3]) : "r"(addr));
}
__device__ __forceinline__ void ldsm_x2(unsigned r[2], unsigned addr) {
    asm volatile(
        "ldmatrix.sync.aligned.m8n8.x2.shared.b16 {%0,%1}, [%2];"
        : "=r"(r[0]), "=r"(r[1]) : "r"(addr));
}
#define CP16(dst, src)  asm volatile("cp.async.cg.shared.global [%0], [%1], 16;" :: "r"(dst), "l"(src) : "memory")
#define CP_COMMIT()     asm volatile("cp.async.commit_group;" ::: "memory")
#define CP_WAIT0()      asm volatile("cp.async.wait_group 0;" ::: "memory")
#define FU(x) __float_as_uint(x)

// ---------------- init ----------------------------------------------------
__global__ void __launch_bounds__(256) init_kernel(
    const float* __restrict__ latent,
    const float* __restrict__ w_ih0, const float* __restrict__ w_fc,
    const float* __restrict__ w_hh0, const float* __restrict__ w_ih1,
    const float* __restrict__ w_hh1)
{
    const int gt = blockIdx.x * 256 + threadIdx.x;     // 0..32767
    float4 z = make_float4(0.f, 0.f, 0.f, 0.f);
    #pragma unroll
    for (int q = 0; q < 4; q++) {                      // zero fp32 state p0
        int i = gt + 32768 * q;
        reinterpret_cast<float4*>(g_h0f[0])[i] = z;
        reinterpret_cast<float4*>(g_h1f[0])[i] = z;
    }
    uint4 z4 = make_uint4(0u, 0u, 0u, 0u);
    #pragma unroll
    for (int q = 0; q < 4; q++) {                      // zero fp16 terms p0
        int i = gt + 32768 * q;
        reinterpret_cast<uint4*>(g_h0t[0])[i] = z4;
        reinterpret_cast<uint4*>(g_h1t[0])[i] = z4;
    }
    if (gt < Bq) g_idx[gt] = -1;
    #pragma unroll
    for (int q = 0; q < 12; q++) {                     // w_ih0 vocab transpose
        int i = gt + 32768 * q;
        int v = i / TH3, g = i - v * TH3;
        g_wvT[i] = w_ih0[g * 512 + 256 + v];
    }
    #pragma unroll
    for (int q = 0; q < 4; q++) {                      // w_fc transpose [k][v]
        int i = gt + 32768 * q;
        int k = i >> 8, v = i & 255;
        g_wfcT[i] = w_fc[v * 512 + k];
    }
    for (int q = 0; q < 24; q++) {                     // fp16 weight splits
        int i = gt + 32768 * q;                        // 786432
        __half a, b;
        split2h(w_hh0[i], a, b); g_w16[0][0][i] = a; g_w16[0][1][i] = b;
        split2h(w_ih1[i], a, b); g_w16[1][0][i] = a; g_w16[1][1][i] = b;
        split2h(w_hh1[i], a, b); g_w16[2][0][i] = a; g_w16[2][1][i] = b;
    }
    for (int q = 0; q < 12; q++) {                     // w_ih0 latent tf32
        int i = gt + 32768 * q;
        int g = i >> 8, c = i & 255;
        float h, l;
        split1(w_ih0[g * 512 + c], h, l);
        g_wah[i] = h; g_wal[i] = l;
    }
    #pragma unroll
    for (int q = 0; q < 8; q++) {                      // latent tf32 split
        int i = gt + 32768 * q;
        float h, l;
        split1(latent[i], h, l);
        g_lath[i] = h; g_latl[i] = l;
    }
}

// ---------------- pre kernel (tf32 mma.sync; proven; runs once) -----------
__global__ void __launch_bounds__(256, 2) pre_kernel(
    const float* __restrict__ bias)
{
    __shared__ __align__(16) float sm[6400];
    const int tid  = threadIdx.x;
    const int lane = tid & 31, warp = tid >> 5;
    const int mw = warp & 1, nw = warp >> 1;
    const int g = lane >> 2, tig = lane & 3;
    const int bb = blockIdx.x;
    const int cs = bb & 15;
    const int rbase = (bb >> 4) * 64;

    float acc[3][2][4];
    #pragma unroll
    for (int nt = 0; nt < 3; nt++)
        #pragma unroll
        for (int mt = 0; mt < 2; mt++)
            #pragma unroll
            for (int i = 0; i < 4; i++) acc[nt][mt][i] = 0.f;

    float* sWh = sm;
    float* sWl = sm + 1920;
    float* sAh = sm + 3840;
    float* sAl = sm + 5120;
    for (int k0 = 0; k0 < LATq; k0 += 16) {
        __syncthreads();
        #pragma unroll
        for (int s = 0; s < 3; s++) {
            int item = tid + 256 * s;
            int half_ = item >= 384;
            int it2  = item - 384 * half_;
            int scol = it2 >> 2, kq = it2 & 3;
            int grow = ((scol >> 5) << 9) + cs * 32 + (scol & 31);
            const float* src = half_ ? g_wal : g_wah;
            float* dst = half_ ? sWl : sWh;
            float4 v = *reinterpret_cast<const float4*>(
                &src[(size_t)grow * LATq + k0 + 4 * kq]);
            *reinterpret_cast<float4*>(&dst[scol * SP + 4 * kq]) = v;
        }
        {
            int row = tid >> 2, kq = tid & 3;
            float4 vh = *reinterpret_cast<const float4*>(
                &g_lath[(size_t)(rbase + row) * LATq + k0 + 4 * kq]);
            float4 vl = *reinterpret_cast<const float4*>(
                &g_latl[(size_t)(rbase + row) * LATq + k0 + 4 * kq]);
            *reinterpret_cast<float4*>(&sAh[row * SP + 4 * kq]) = vh;
            *reinterpret_cast<float4*>(&sAl[row * SP + 4 * kq]) = vl;
        }
        __syncthreads();
        #pragma unroll
        for (int k8o = 0; k8o < 16; k8o += 8) {
            unsigned ah[2][4], al[2][4];
            #pragma unroll
            for (int mt = 0; mt < 2; mt++) {
                int r0 = 32 * mw + 16 * mt + g;
                ah[mt][0] = FU(sAh[r0 * SP + k8o + tig]);
                ah[mt][1] = FU(sAh[(r0 + 8) * SP + k8o + tig]);
                ah[mt][2] = FU(sAh[r0 * SP + k8o + tig + 4]);
                ah[mt][3] = FU(sAh[(r0 + 8) * SP + k8o + tig + 4]);
                al[mt][0] = FU(sAl[r0 * SP + k8o + tig]);
                al[mt][1] = FU(sAl[(r0 + 8) * SP + k8o + tig]);
                al[mt][2] = FU(sAl[r0 * SP + k8o + tig + 4]);
                al[mt][3] = FU(sAl[(r0 + 8) * SP + k8o + tig + 4]);
            }
            #pragma unroll
            for (int nt = 0; nt < 3; nt++) {
                int scol = nt * 32 + nw * 8 + g;
                unsigned bh0 = FU(sWh[scol * SP + k8o + tig]);
                unsigned bh1 = FU(sWh[scol * SP + k8o + tig + 4]);
                unsigned bl0 = FU(sWl[scol * SP + k8o + tig]);
                unsigned bl1 = FU(sWl[scol * SP + k8o + tig + 4]);
                #pragma unroll
                for (int mt = 0; mt < 2; mt++) {
                    mma_tf32(acc[nt][mt], ah[mt], bh0, bh1);
                    mma_tf32(acc[nt][mt], ah[mt], bl0, bl1);
                    mma_tf32(acc[nt][mt], al[mt], bh0, bh1);
                }
            }
        }
    }
    #pragma unroll
    for (int nt = 0; nt < 3; nt++) {
        int gc = nt * 512 + cs * 32 + nw * 8 + 2 * tig;
        float b0 = bias[gc], b1 = bias[gc + 1];
        #pragma unroll
        for (int mt = 0; mt < 2; mt++) {
            int r0 = rbase + 32 * mw + 16 * mt + g;
            g_pre[(size_t)r0 * TH3 + gc]           = acc[nt][mt][0] + b0;
            g_pre[(size_t)r0 * TH3 + gc + 1]       = acc[nt][mt][1] + b1;
            g_pre[(size_t)(r0 + 8) * TH3 + gc]     = acc[nt][mt][2] + b0;
            g_pre[(size_t)(r0 + 8) * TH3 + gc + 1] = acc[nt][mt][3] + b1;
        }
    }
}

// ---------------- fp16 GEMM: 512 threads, cp.async db + ldmatrix ----------
// Block tile 64 rows x 96 cols. 16 warps: mw=warp&3 (16-row quarter),
// nw=warp>>2 (8-col subtile per gate). Warp tile 16x24, acc[3][4].
// Panel (words): W terms @ t*1152 + scol*12 + w ; A terms @ 2304 + t*768
// + row*12 + w ; panel 3840 words (15360 B), two buffers.
__device__ __forceinline__ void gemm16_ca(
    float acc[3][4],
    const __half* __restrict__ A0, const __half* __restrict__ A1,
    int rbase,
    const __half* __restrict__ W0, const __half* __restrict__ W1,
    int cs, unsigned* sm)
{
    const int tid  = threadIdx.x;
    const int lane = tid & 31, warp = tid >> 5;
    const int mw = warp & 3, nw = warp >> 2;
    const unsigned sbase = (unsigned)__cvta_generic_to_shared(sm);

    // panel-load slots (640 granules over 512 threads: slot0 all, slot1 tid<128)
    const __half* src[2];
    unsigned dstb[2];
    bool vld[2];
    #pragma unroll
    for (int s = 0; s < 2; s++) {
        int i = tid + 512 * s;
        vld[s] = (i < 640);
        int ii = vld[s] ? i : 0;
        if (ii < 384) {
            int term = ii / 192, rem = ii - term * 192;
            int scol = rem >> 1, gr = rem & 1;
            int gcol = ((scol >> 5) << 9) + cs * 32 + (scol & 31);
            src[s]  = (term ? W1 : W0) + (size_t)gcol * Hq + gr * 8;
            dstb[s] = sbase + ((term * 1152 + scol * 12 + gr * 4) << 2);
        } else {
            int j = ii - 384;                   // 0..255
            int term = j >> 7, rem = j & 127;
            int row = rem >> 1, gr = rem & 1;
            src[s]  = (term ? A1 : A0) + (size_t)(rbase + row) * Hq + gr * 8;
            dstb[s] = sbase + ((2304 + term * 768 + row * 12 + gr * 4) << 2);
        }
    }

    // ldmatrix per-lane addresses (byte offsets inside one panel buffer)
    const int arow = (lane & 7) + 8 * ((lane >> 3) & 1);
    const int akw  = 4 * (lane >> 4);
    const int brow = lane & 7;
    const int bkw  = 4 * ((lane >> 3) & 1);
    unsigned aaddr[2], baddr[2][3];
    #pragma unroll
    for (int term = 0; term < 2; term++) {
        aaddr[term] = sbase +
            ((2304 + term * 768 + (16 * mw + arow) * 12 + akw) << 2);
        #pragma unroll
        for (int nt = 0; nt < 3; nt++)
            baddr[term][nt] = sbase +
                ((term * 1152 + (nt * 32 + nw * 8 + brow) * 12 + bkw) << 2);
    }

    // prologue: fill buf0
    #pragma unroll
    for (int s = 0; s < 2; s++)
        if (vld[s]) CP16(dstb[s], src[s]);
    CP_COMMIT();
    CP_WAIT0();
    __syncthreads();

    for (int k0 = 0; k0 < Hq; k0 += 16) {
        const bool more = (k0 + 16) < Hq;
        const unsigned bufo = ((k0 >> 4) & 1) * 15360u;
        if (more) {           // stage next panel into the other buffer
            const unsigned nbo = 15360u - bufo;
            #pragma unroll
            for (int s = 0; s < 2; s++)
                if (vld[s]) CP16(dstb[s] + nbo, src[s] + k0 + 16);
            CP_COMMIT();
        }
        unsigned a[2][4], b[2][3][2];
        #pragma unroll
        for (int term = 0; term < 2; term++) {
            ldsm_x4(a[term], aaddr[term] + bufo);
            #pragma unroll
            for (int nt = 0; nt < 3; nt++)
                ldsm_x2(b[term][nt], baddr[term][nt] + bufo);
        }
        #pragma unroll
        for (int nt = 0; nt < 3; nt++) {
            mma_f16(acc[nt], a[0], b[0][nt][0], b[0][nt][1]);   // h1*w1
            mma_f16(acc[nt], a[0], b[1][nt][0], b[1][nt][1]);   // h1*w2
            mma_f16(acc[nt], a[1], b[0][nt][0], b[0][nt][1]);   // h2*w1
        }
        if (more) {
            CP_WAIT0();
            __syncthreads();
        }
    }
    __syncthreads();   // protect smem for a subsequent gemm call
}

#define ACC_ZERO3(acc)                                       \
    _Pragma("unroll")                                        \
    for (int nt = 0; nt < 3; nt++)                           \
        _Pragma("unroll")                                    \
        for (int i = 0; i < 4; i++) acc[nt][i] = 0.f;

// ---------------- stage A: layer-0 GRU (one-hot gather) -------------------
__global__ void __launch_bounds__(512, 2) stepA_kernel(
    const float* __restrict__ b_hh0, int t)
{
    __shared__ __align__(16) unsigned sm[7680];
    const int pr = t & 1, pw = 1 - pr;
    const int tid  = threadIdx.x;
    const int lane = tid & 31, warp = tid >> 5;
    const int mw = warp & 3, nw = warp >> 2;
    const int g = lane >> 2, tig = lane & 3;
    const int bb = blockIdx.x;
    const int cs = bb & 15;
    const int rbase = (bb >> 4) * 64;

    float acc[3][4];
    ACC_ZERO3(acc)
    gemm16_ca(acc, g_h0t[pr][0], g_h0t[pr][1], rbase,
              g_w16[0][0], g_w16[0][1], cs, sm);

    const int hb = cs * 32 + nw * 8 + 2 * tig;
    #pragma unroll
    for (int rr = 0; rr < 2; rr++) {
        int b = rbase + 16 * mw + g + 8 * rr;
        int ix = g_idx[b];
        #pragma unroll
        for (int cc = 0; cc < 2; cc++) {
            int hp = hb + cc;
            float ir  = g_pre[(size_t)b * TH3 + hp];
            float iz  = g_pre[(size_t)b * TH3 + 512 + hp];
            float in_ = g_pre[(size_t)b * TH3 + 1024 + hp];
            if (ix >= 0) {
                ir  += g_wvT[(size_t)ix * TH3 + hp];
                iz  += g_wvT[(size_t)ix * TH3 + 512 + hp];
                in_ += g_wvT[(size_t)ix * TH3 + 1024 + hp];
            }
            int ai = 2 * rr + cc;
            float R = sigmoidf_(ir + acc[0][ai] + b_hh0[hp]);
            float Z = sigmoidf_(iz + acc[1][ai] + b_hh0[512 + hp]);
            float N = tanhf(in_ + R * (acc[2][ai] + b_hh0[1024 + hp]));
            float hold = g_h0f[pr][(size_t)b * Hq + hp];
            float val = (1.f - Z) * N + Z * hold;
            size_t o = (size_t)b * Hq + hp;
            g_h0f[pw][o] = val;
            __half v1, v2;
            split2h(val, v1, v2);
            g_h0t[pw][0][o] = v1;
            g_h0t[pw][1][o] = v2;
        }
    }
}

// ---------------- stage B: layer-1 GRU, two sequential GEMMs --------------
__global__ void __launch_bounds__(512, 2) stepB_kernel(
    const float* __restrict__ b_ih1, const float* __restrict__ b_hh1, int t)
{
    __shared__ __align__(16) unsigned sm[7680];
    const int pr = t & 1, pw = 1 - pr;
    const int tid  = threadIdx.x;
    const int lane = tid & 31, warp = tid >> 5;
    const int mw = warp & 3, nw = warp >> 2;
    const int g = lane >> 2, tig = lane & 3;
    const int bb = blockIdx.x;
    const int cs = bb & 15;
    const int rbase = (bb >> 4) * 64;

    float ai_[3][4], ah_[3][4];
    ACC_ZERO3(ai_)
    ACC_ZERO3(ah_)
    gemm16_ca(ai_, g_h0t[pw][0], g_h0t[pw][1], rbase,
              g_w16[1][0], g_w16[1][1], cs, sm);
    gemm16_ca(ah_, g_h1t[pr][0], g_h1t[pr][1], rbase,
              g_w16[2][0], g_w16[2][1], cs, sm);

    const int hb = cs * 32 + nw * 8 + 2 * tig;
    #pragma unroll
    for (int rr = 0; rr < 2; rr++) {
        int b = rbase + 16 * mw + g + 8 * rr;
        #pragma unroll
        for (int cc = 0; cc < 2; cc++) {
            int hp = hb + cc;
            int aidx = 2 * rr + cc;
            float R = sigmoidf_(ai_[0][aidx] + b_ih1[hp]
                              + ah_[0][aidx] + b_hh1[hp]);
            float Z = sigmoidf_(ai_[1][aidx] + b_ih1[512 + hp]
                              + ah_[1][aidx] + b_hh1[512 + hp]);
            float N = tanhf(ai_[2][aidx] + b_ih1[1024 + hp]
                          + R * (ah_[2][aidx] + b_hh1[1024 + hp]));
            float hold = g_h1f[pr][(size_t)b * Hq + hp];
            float val = (1.f - Z) * N + Z * hold;
            size_t o = (size_t)b * Hq + hp;
            g_h1f[pw][o] = val;
            __half v1, v2;
            split2h(val, v1, v2);
            g_h1t[pw][0][o] = v1;
            g_h1t[pw][1][o] = v2;
        }
    }
}

// ---------------- stage C: logits + argmax + one-hot ----------------------
__global__ void __launch_bounds__(256) stepC_kernel(
    const float* __restrict__ b_fc, float* __restrict__ out, int t)
{
    __shared__ float sHL[8 * Hq];
    __shared__ float sLOG[8 * Vq];
    __shared__ int   sIDX[8];
    const int pw = 1 - (t & 1);
    const int tid = threadIdx.x;
    const int tx  = tid & 31;
    const int ty  = tid >> 5;
    const int rb  = blockIdx.x * 8;

    #pragma unroll
    for (int q = 0; q < 4; q++) {
        int f4 = tid + 256 * q;
        int r  = f4 >> 7;
        int kq = f4 & 127;
        float4 v = *reinterpret_cast<const float4*>(
            &g_h1f[pw][(size_t)(rb + r) * Hq + 4 * kq]);
        *reinterpret_cast<float4*>(&sHL[r * Hq + 4 * kq]) = v;
    }
    __syncthreads();

    float acc[8];
    #pragma unroll
    for (int r = 0; r < 8; r++) acc[r] = 0.f;
    #pragma unroll 8
    for (int k = 0; k < Hq; k++) {
        float wv = g_wfcT[k * Vq + tid];
        #pragma unroll
        for (int r = 0; r < 8; r++) acc[r] += sHL[r * Hq + k] * wv;
    }
    float bf = b_fc[tid];
    #pragma unroll
    for (int r = 0; r < 8; r++) sLOG[r * Vq + tid] = acc[r] + bf;
    __syncthreads();

    {   // warp ty reduces row ty, first-max tie-break (matches jnp.argmax)
        int row = ty;
        float bv = -3.4e38f;
        int   bi = 0;
        #pragma unroll
        for (int m = 0; m < 8; m++) {
            int idx = tx + 32 * m;
            float v = sLOG[row * Vq + idx];
            if (v > bv) { bv = v; bi = idx; }
        }
        #pragma unroll
        for (int off = 16; off > 0; off >>= 1) {
            float ov = __shfl_down_sync(0xffffffffu, bv, off);
            int   oi = __shfl_down_sync(0xffffffffu, bi, off);
            if (ov > bv || (ov == bv && oi < bi)) { bv = ov; bi = oi; }
        }
        if (tx == 0) sIDX[row] = bi;
    }
    __syncthreads();
    #pragma unroll
    for (int r = 0; r < 8; r++) {
        out[(size_t)(rb + r) * (Tq * Vq) + t * Vq + tid] =
            (tid == sIDX[r]) ? 1.0f : 0.0f;
    }
    if (tid < 8) g_idx[rb + tid] = sIDX[tid];
}

// ---------------- launch ---------------------------------------------------
extern "C" void kernel_launch(void* const* d_in, const int* in_sizes, int n_in,
                              void* d_out, int out_size)
{
    const float* latent = (const float*)d_in[0];
    // d_in[1] enthalpy: unused on freerun path
    const float* w_ih0  = (const float*)d_in[2];
    const float* w_hh0  = (const float*)d_in[3];
    const float* b_ih0  = (const float*)d_in[4];
    const float* b_hh0  = (const float*)d_in[5];
    const float* w_ih1  = (const float*)d_in[6];
    const float* w_hh1  = (const float*)d_in[7];
    const float* b_ih1  = (const float*)d_in[8];
    const float* b_hh1  = (const float*)d_in[9];
    const float* w_fc   = (const float*)d_in[10];
    const float* b_fc   = (const float*)d_in[11];
    float* out = (float*)d_out;

    init_kernel<<<128, 256>>>(latent, w_ih0, w_fc, w_hh0, w_ih1, w_hh1);
    pre_kernel<<<256, 256>>>(b_ih0);
    for (int t = 0; t < Tq; t++) {
        stepA_kernel<<<256, 512>>>(b_hh0, t);
        stepB_kernel<<<256, 512>>>(b_ih1, b_hh1, t);
        stepC_kernel<<<128, 256>>>(b_fc, out, t);
    }
}

// round 17
// speedup vs baseline: 1.0715x; 1.0715x over previous
#include <cuda_runtime.h>
#include <cuda_fp16.h>
#include <math.h>

// Decoder free-run greedy decode. B=1024, T=64, V=256, LAT=256, H=512, L=2.
// R17: R15 tiling (256 thr, warp tile 32x24, ldmatrix + cp.async) with a
// 3-stage cp.async ring (wait_group 1): panel copies get 2 iterations of
// flight time, removing per-iteration latency exposure.
// Math/MMA order identical to R15 (rel_err = 0 validated).
// pre_kernel keeps the proven tf32 route (runs once). Multi-launch,
// graph-capturable. __device__ symbols referenced from device code only.

#define Bq   1024
#define Hq   512
#define TH3  1536
#define Vq   256
#define LATq 256
#define Tq   64
#define SP   20      // tf32 pre-kernel smem pitch

// ---------------- device scratch ------------------------------------------
__device__ float g_pre[Bq * TH3];
__device__ float g_wvT[Vq * TH3];          // w_ih0 vocab cols [v][gate3H]
__device__ float g_wfcT[Hq * Vq];          // w_fc transposed [k][v]
__device__ float g_h0f[2][Bq * Hq], g_h1f[2][Bq * Hq];
__device__ int   g_idx[Bq];
// fp16 2-term splits: weights [mat: 0=whh0 1=wih1 2=whh1][term]
__device__ __align__(16) __half g_w16[3][2][TH3 * Hq];
__device__ __align__(16) __half g_h0t[2][2][Bq * Hq];   // [parity][term]
__device__ __align__(16) __half g_h1t[2][2][Bq * Hq];
// tf32 split data for pre_kernel
__device__ float g_wah[TH3 * LATq], g_wal[TH3 * LATq];
__device__ float g_lath[Bq * LATq], g_latl[Bq * LATq];

__device__ __forceinline__ float sigmoidf_(float x) {
    return 1.0f / (1.0f + expf(-x));
}
__device__ __forceinline__ unsigned cvt_tf32(float x) {
    unsigned r;
    asm("cvt.rna.tf32.f32 %0, %1;" : "=r"(r) : "f"(x));
    return r;
}
__device__ __forceinline__ void split1(float x, float &h, float &l) {
    float hf = __uint_as_float(cvt_tf32(x));
    h = hf;
    l = __uint_as_float(cvt_tf32(x - hf));
}
__device__ __forceinline__ void split2h(float x, __half &a, __half &b) {
    a = __float2half_rn(x);
    b = __float2half_rn(x - __half2float(a));
}
__device__ __forceinline__ void mma_tf32(float c[4], const unsigned a[4],
                                         unsigned b0, unsigned b1) {
    asm volatile(
        "mma.sync.aligned.m16n8k8.row.col.f32.tf32.tf32.f32 "
        "{%0,%1,%2,%3}, {%4,%5,%6,%7}, {%8,%9}, {%0,%1,%2,%3};"
        : "+f"(c[0]), "+f"(c[1]), "+f"(c[2]), "+f"(c[3])
        : "r"(a[0]), "r"(a[1]), "r"(a[2]), "r"(a[3]), "r"(b0), "r"(b1));
}
__device__ __forceinline__ void mma_f16(float c[4], const unsigned a[4],
                                        unsigned b0, unsigned b1) {
    asm volatile(
        "mma.sync.aligned.m16n8k16.row.col.f32.f16.f16.f32 "
        "{%0,%1,%2,%3}, {%4,%5,%6,%7}, {%8,%9}, {%0,%1,%2,%3};"
        : "+f"(c[0]), "+f"(c[1]), "+f"(c[2]), "+f"(c[3])
        : "r"(a[0]), "r"(a[1]), "r"(a[2]), "r"(a[3]), "r"(b0), "r"(b1));
}
__device__ __forceinline__ void ldsm_x4(unsigned r[4], unsigned addr) {
    asm volatile(
        "ldmatrix.sync.aligned.m8n8.x4.shared.b16 {%0,%1,%2,%3}, [%4];"
        : "=r"(r[0]), "=r"(r[1]), "=r"(r[2]), "=r"(r[3]) : "r"(addr));
}
__device__ __forceinline__ void ldsm_x2(unsigned r[2], unsigned addr) {
    asm volatile(
        "ldmatrix.sync.aligned.m8n8.x2.shared.b16 {%0,%1}, [%2];"
        : "=r"(r[0]), "=r"(r[1]) : "r"(addr));
}
#define CP16(dst, src)  asm volatile("cp.async.cg.shared.global [%0], [%1], 16;" :: "r"(dst), "l"(src) : "memory")
#define CP_COMMIT()     asm volatile("cp.async.commit_group;" ::: "memory")
#define CP_WAIT0()      asm volatile("cp.async.wait_group 0;" ::: "memory")
#define CP_WAIT1()      asm volatile("cp.async.wait_group 1;" ::: "memory")
#define FU(x) __float_as_uint(x)

// ---------------- init ----------------------------------------------------
__global__ void __launch_bounds__(256) init_kernel(
    const float* __restrict__ latent,
    const float* __restrict__ w_ih0, const float* __restrict__ w_fc,
    const float* __restrict__ w_hh0, const float* __restrict__ w_ih1,
    const float* __restrict__ w_hh1)
{
    const int gt = blockIdx.x * 256 + threadIdx.x;     // 0..32767
    float4 z = make_float4(0.f, 0.f, 0.f, 0.f);
    #pragma unroll
    for (int q = 0; q < 4; q++) {                      // zero fp32 state p0
        int i = gt + 32768 * q;
        reinterpret_cast<float4*>(g_h0f[0])[i] = z;
        reinterpret_cast<float4*>(g_h1f[0])[i] = z;
    }
    uint4 z4 = make_uint4(0u, 0u, 0u, 0u);
    #pragma unroll
    for (int q = 0; q < 4; q++) {                      // zero fp16 terms p0
        int i = gt + 32768 * q;
        reinterpret_cast<uint4*>(g_h0t[0])[i] = z4;
        reinterpret_cast<uint4*>(g_h1t[0])[i] = z4;
    }
    if (gt < Bq) g_idx[gt] = -1;
    #pragma unroll
    for (int q = 0; q < 12; q++) {                     // w_ih0 vocab transpose
        int i = gt + 32768 * q;
        int v = i / TH3, g = i - v * TH3;
        g_wvT[i] = w_ih0[g * 512 + 256 + v];
    }
    #pragma unroll
    for (int q = 0; q < 4; q++) {                      // w_fc transpose [k][v]
        int i = gt + 32768 * q;
        int k = i >> 8, v = i & 255;
        g_wfcT[i] = w_fc[v * 512 + k];
    }
    for (int q = 0; q < 24; q++) {                     // fp16 weight splits
        int i = gt + 32768 * q;                        // 786432
        __half a, b;
        split2h(w_hh0[i], a, b); g_w16[0][0][i] = a; g_w16[0][1][i] = b;
        split2h(w_ih1[i], a, b); g_w16[1][0][i] = a; g_w16[1][1][i] = b;
        split2h(w_hh1[i], a, b); g_w16[2][0][i] = a; g_w16[2][1][i] = b;
    }
    for (int q = 0; q < 12; q++) {                     // w_ih0 latent tf32
        int i = gt + 32768 * q;
        int g = i >> 8, c = i & 255;
        float h, l;
        split1(w_ih0[g * 512 + c], h, l);
        g_wah[i] = h; g_wal[i] = l;
    }
    #pragma unroll
    for (int q = 0; q < 8; q++) {                      // latent tf32 split
        int i = gt + 32768 * q;
        float h, l;
        split1(latent[i], h, l);
        g_lath[i] = h; g_latl[i] = l;
    }
}

// ---------------- pre kernel (tf32 mma.sync; proven; runs once) -----------
__global__ void __launch_bounds__(256, 2) pre_kernel(
    const float* __restrict__ bias)
{
    __shared__ __align__(16) float sm[6400];
    const int tid  = threadIdx.x;
    const int lane = tid & 31, warp = tid >> 5;
    const int mw = warp & 1, nw = warp >> 1;
    const int g = lane >> 2, tig = lane & 3;
    const int bb = blockIdx.x;
    const int cs = bb & 15;
    const int rbase = (bb >> 4) * 64;

    float acc[3][2][4];
    #pragma unroll
    for (int nt = 0; nt < 3; nt++)
        #pragma unroll
        for (int mt = 0; mt < 2; mt++)
            #pragma unroll
            for (int i = 0; i < 4; i++) acc[nt][mt][i] = 0.f;

    float* sWh = sm;
    float* sWl = sm + 1920;
    float* sAh = sm + 3840;
    float* sAl = sm + 5120;
    for (int k0 = 0; k0 < LATq; k0 += 16) {
        __syncthreads();
        #pragma unroll
        for (int s = 0; s < 3; s++) {
            int item = tid + 256 * s;
            int half_ = item >= 384;
            int it2  = item - 384 * half_;
            int scol = it2 >> 2, kq = it2 & 3;
            int grow = ((scol >> 5) << 9) + cs * 32 + (scol & 31);
            const float* src = half_ ? g_wal : g_wah;
            float* dst = half_ ? sWl : sWh;
            float4 v = *reinterpret_cast<const float4*>(
                &src[(size_t)grow * LATq + k0 + 4 * kq]);
            *reinterpret_cast<float4*>(&dst[scol * SP + 4 * kq]) = v;
        }
        {
            int row = tid >> 2, kq = tid & 3;
            float4 vh = *reinterpret_cast<const float4*>(
                &g_lath[(size_t)(rbase + row) * LATq + k0 + 4 * kq]);
            float4 vl = *reinterpret_cast<const float4*>(
                &g_latl[(size_t)(rbase + row) * LATq + k0 + 4 * kq]);
            *reinterpret_cast<float4*>(&sAh[row * SP + 4 * kq]) = vh;
            *reinterpret_cast<float4*>(&sAl[row * SP + 4 * kq]) = vl;
        }
        __syncthreads();
        #pragma unroll
        for (int k8o = 0; k8o < 16; k8o += 8) {
            unsigned ah[2][4], al[2][4];
            #pragma unroll
            for (int mt = 0; mt < 2; mt++) {
                int r0 = 32 * mw + 16 * mt + g;
                ah[mt][0] = FU(sAh[r0 * SP + k8o + tig]);
                ah[mt][1] = FU(sAh[(r0 + 8) * SP + k8o + tig]);
                ah[mt][2] = FU(sAh[r0 * SP + k8o + tig + 4]);
                ah[mt][3] = FU(sAh[(r0 + 8) * SP + k8o + tig + 4]);
                al[mt][0] = FU(sAl[r0 * SP + k8o + tig]);
                al[mt][1] = FU(sAl[(r0 + 8) * SP + k8o + tig]);
                al[mt][2] = FU(sAl[r0 * SP + k8o + tig + 4]);
                al[mt][3] = FU(sAl[(r0 + 8) * SP + k8o + tig + 4]);
            }
            #pragma unroll
            for (int nt = 0; nt < 3; nt++) {
                int scol = nt * 32 + nw * 8 + g;
                unsigned bh0 = FU(sWh[scol * SP + k8o + tig]);
                unsigned bh1 = FU(sWh[scol * SP + k8o + tig + 4]);
                unsigned bl0 = FU(sWl[scol * SP + k8o + tig]);
                unsigned bl1 = FU(sWl[scol * SP + k8o + tig + 4]);
                #pragma unroll
                for (int mt = 0; mt < 2; mt++) {
                    mma_tf32(acc[nt][mt], ah[mt], bh0, bh1);
                    mma_tf32(acc[nt][mt], ah[mt], bl0, bl1);
                    mma_tf32(acc[nt][mt], al[mt], bh0, bh1);
                }
            }
        }
    }
    #pragma unroll
    for (int nt = 0; nt < 3; nt++) {
        int gc = nt * 512 + cs * 32 + nw * 8 + 2 * tig;
        float b0 = bias[gc], b1 = bias[gc + 1];
        #pragma unroll
        for (int mt = 0; mt < 2; mt++) {
            int r0 = rbase + 32 * mw + 16 * mt + g;
            g_pre[(size_t)r0 * TH3 + gc]           = acc[nt][mt][0] + b0;
            g_pre[(size_t)r0 * TH3 + gc + 1]       = acc[nt][mt][1] + b1;
            g_pre[(size_t)(r0 + 8) * TH3 + gc]     = acc[nt][mt][2] + b0;
            g_pre[(size_t)(r0 + 8) * TH3 + gc + 1] = acc[nt][mt][3] + b1;
        }
    }
}

// ---------------- fp16 GEMM: 3-stage cp.async ring + ldmatrix -------------
// Panel (words): W terms @ t*1152 + scol*12 + w ; A terms @ 2304 + t*768
// + row*12 + w ; panel 3840 words (15360 B), THREE buffers (ring).
__device__ __forceinline__ void gemm16_ca(
    float acc[3][2][4],
    const __half* __restrict__ A0, const __half* __restrict__ A1,
    int rbase,
    const __half* __restrict__ W0, const __half* __restrict__ W1,
    int cs, unsigned* sm)
{
    const int tid  = threadIdx.x;
    const int lane = tid & 31, warp = tid >> 5;
    const int mw = warp & 1, nw = warp >> 1;
    const unsigned sbase = (unsigned)__cvta_generic_to_shared(sm);

    // panel-load slots (640 granules, <=3 per thread)
    const __half* src[3];
    unsigned dstb[3];
    bool vld[3];
    #pragma unroll
    for (int s = 0; s < 3; s++) {
        int i = tid + 256 * s;
        vld[s] = (i < 640);
        int ii = vld[s] ? i : 0;
        if (ii < 384) {
            int term = ii / 192, rem = ii - term * 192;
            int scol = rem >> 1, gr = rem & 1;
            int gcol = ((scol >> 5) << 9) + cs * 32 + (scol & 31);
            src[s]  = (term ? W1 : W0) + (size_t)gcol * Hq + gr * 8;
            dstb[s] = sbase + ((term * 1152 + scol * 12 + gr * 4) << 2);
        } else {
            int j = ii - 384;
            int term = j >> 7, rem = j & 127;
            int row = rem >> 1, gr = rem & 1;
            src[s]  = (term ? A1 : A0) + (size_t)(rbase + row) * Hq + gr * 8;
            dstb[s] = sbase + ((2304 + term * 768 + row * 12 + gr * 4) << 2);
        }
    }

    // ldmatrix per-lane addresses (byte offsets inside one panel buffer)
    const int arow = (lane & 7) + 8 * ((lane >> 3) & 1);
    const int akw  = 4 * (lane >> 4);
    const int brow = lane & 7;
    const int bkw  = 4 * ((lane >> 3) & 1);
    unsigned aaddr[2][2], baddr[2][3];
    #pragma unroll
    for (int term = 0; term < 2; term++) {
        #pragma unroll
        for (int mt = 0; mt < 2; mt++)
            aaddr[term][mt] = sbase +
                ((2304 + term * 768 +
                  (32 * mw + 16 * mt + arow) * 12 + akw) << 2);
        #pragma unroll
        for (int nt = 0; nt < 3; nt++)
            baddr[term][nt] = sbase +
                ((term * 1152 + (nt * 32 + nw * 8 + brow) * 12 + bkw) << 2);
    }

    // prologue: stage panels 0 and 1 into buf0, buf1
    #pragma unroll
    for (int s = 0; s < 3; s++)
        if (vld[s]) CP16(dstb[s], src[s]);
    CP_COMMIT();
    #pragma unroll
    for (int s = 0; s < 3; s++)
        if (vld[s]) CP16(dstb[s] + 15360u, src[s] + 16);
    CP_COMMIT();
    CP_WAIT1();            // buf0 ready (buf1 may still be in flight)
    __syncthreads();

    unsigned bufo = 0;     // byte offset of current buffer; ring of 3
    for (int it = 0; it < 32; it++) {
        const int k0 = it * 16;
        // stage panel it+2 into the buffer 2 ahead in the ring
        if (it + 2 < 32) {
            unsigned fo = bufo + 30720u;
            if (fo >= 46080u) fo -= 46080u;
            #pragma unroll
            for (int s = 0; s < 3; s++)
                if (vld[s]) CP16(dstb[s] + fo, src[s] + k0 + 32);
        }
        CP_COMMIT();       // commit every iter (possibly empty) for counting
        unsigned a[2][2][4], b[2][3][2];
        #pragma unroll
        for (int term = 0; term < 2; term++) {
            #pragma unroll
            for (int mt = 0; mt < 2; mt++)
                ldsm_x4(a[term][mt], aaddr[term][mt] + bufo);
            #pragma unroll
            for (int nt = 0; nt < 3; nt++)
                ldsm_x2(b[term][nt], baddr[term][nt] + bufo);
        }
        #pragma unroll
        for (int nt = 0; nt < 3; nt++)
            #pragma unroll
            for (int mt = 0; mt < 2; mt++) {
                mma_f16(acc[nt][mt], a[0][mt], b[0][nt][0], b[0][nt][1]);
                mma_f16(acc[nt][mt], a[0][mt], b[1][nt][0], b[1][nt][1]);
                mma_f16(acc[nt][mt], a[1][mt], b[0][nt][0], b[0][nt][1]);
            }
        CP_WAIT1();        // panel it+1 complete (<=1 group pending)
        __syncthreads();
        bufo += 15360u;
        if (bufo >= 46080u) bufo = 0;
    }
    CP_WAIT0();            // drain (empty tail groups)
    __syncthreads();       // protect smem for a subsequent gemm call
}

#define ACC_ZERO(acc)                                        \
    _Pragma("unroll")                                        \
    for (int nt = 0; nt < 3; nt++)                           \
        _Pragma("unroll")                                    \
        for (int mt = 0; mt < 2; mt++)                       \
            _Pragma("unroll")                                \
            for (int i = 0; i < 4; i++) acc[nt][mt][i] = 0.f;

// ---------------- stage A: layer-0 GRU (one-hot gather) -------------------
__global__ void __launch_bounds__(256, 2) stepA_kernel(
    const float* __restrict__ b_hh0, int t)
{
    __shared__ __align__(16) unsigned sm[11520];   // 3 x 3840 words
    const int pr = t & 1, pw = 1 - pr;
    const int tid  = threadIdx.x;
    const int lane = tid & 31, warp = tid >> 5;
    const int mw = warp & 1, nw = warp >> 1;
    const int g = lane >> 2, tig = lane & 3;
    const int bb = blockIdx.x;
    const int cs = bb & 15;
    const int rbase = (bb >> 4) * 64;

    float acc[3][2][4];
    ACC_ZERO(acc)
    gemm16_ca(acc, g_h0t[pr][0], g_h0t[pr][1], rbase,
              g_w16[0][0], g_w16[0][1], cs, sm);

    const int hb = cs * 32 + nw * 8 + 2 * tig;
    float bR0 = b_hh0[hb],        bR1 = b_hh0[hb + 1];
    float bZ0 = b_hh0[512 + hb],  bZ1 = b_hh0[512 + hb + 1];
    float bN0 = b_hh0[1024 + hb], bN1 = b_hh0[1024 + hb + 1];
    #pragma unroll
    for (int mt = 0; mt < 2; mt++) {
        #pragma unroll
        for (int rr = 0; rr < 2; rr++) {
            int b = rbase + 32 * mw + 16 * mt + g + 8 * rr;
            int ix = g_idx[b];
            #pragma unroll
            for (int cc = 0; cc < 2; cc++) {
                int hp = hb + cc;
                float ir  = g_pre[(size_t)b * TH3 + hp];
                float iz  = g_pre[(size_t)b * TH3 + 512 + hp];
                float in_ = g_pre[(size_t)b * TH3 + 1024 + hp];
                if (ix >= 0) {
                    ir  += g_wvT[(size_t)ix * TH3 + hp];
                    iz  += g_wvT[(size_t)ix * TH3 + 512 + hp];
                    in_ += g_wvT[(size_t)ix * TH3 + 1024 + hp];
                }
                int ai = 2 * rr + cc;
                float R = sigmoidf_(ir + acc[0][mt][ai] + (cc ? bR1 : bR0));
                float Z = sigmoidf_(iz + acc[1][mt][ai] + (cc ? bZ1 : bZ0));
                float N = tanhf(in_ + R * (acc[2][mt][ai] + (cc ? bN1 : bN0)));
                float hold = g_h0f[pr][(size_t)b * Hq + hp];
                float val = (1.f - Z) * N + Z * hold;
                size_t o = (size_t)b * Hq + hp;
                g_h0f[pw][o] = val;
                __half v1, v2;
                split2h(val, v1, v2);
                g_h0t[pw][0][o] = v1;
                g_h0t[pw][1][o] = v2;
            }
        }
    }
}

// ---------------- stage B: layer-1 GRU, two sequential GEMMs --------------
__global__ void __launch_bounds__(256, 2) stepB_kernel(
    const float* __restrict__ b_ih1, const float* __restrict__ b_hh1, int t)
{
    __shared__ __align__(16) unsigned sm[11520];   // 3 x 3840 words
    const int pr = t & 1, pw = 1 - pr;
    const int tid  = threadIdx.x;
    const int lane = tid & 31, warp = tid >> 5;
    const int mw = warp & 1, nw = warp >> 1;
    const int g = lane >> 2, tig = lane & 3;
    const int bb = blockIdx.x;
    const int cs = bb & 15;
    const int rbase = (bb >> 4) * 64;

    float ai_[3][2][4], ah_[3][2][4];
    ACC_ZERO(ai_)
    ACC_ZERO(ah_)
    gemm16_ca(ai_, g_h0t[pw][0], g_h0t[pw][1], rbase,
              g_w16[1][0], g_w16[1][1], cs, sm);
    gemm16_ca(ah_, g_h1t[pr][0], g_h1t[pr][1], rbase,
              g_w16[2][0], g_w16[2][1], cs, sm);

    const int hb = cs * 32 + nw * 8 + 2 * tig;
    float iR0 = b_ih1[hb],        iR1 = b_ih1[hb + 1];
    float iZ0 = b_ih1[512 + hb],  iZ1 = b_ih1[512 + hb + 1];
    float iN0 = b_ih1[1024 + hb], iN1 = b_ih1[1024 + hb + 1];
    float hR0 = b_hh1[hb],        hR1 = b_hh1[hb + 1];
    float hZ0 = b_hh1[512 + hb],  hZ1 = b_hh1[512 + hb + 1];
    float hN0 = b_hh1[1024 + hb], hN1 = b_hh1[1024 + hb + 1];
    #pragma unroll
    for (int mt = 0; mt < 2; mt++) {
        #pragma unroll
        for (int rr = 0; rr < 2; rr++) {
            int b = rbase + 32 * mw + 16 * mt + g + 8 * rr;
            #pragma unroll
            for (int cc = 0; cc < 2; cc++) {
                int hp = hb + cc;
                int aidx = 2 * rr + cc;
                float R = sigmoidf_(ai_[0][mt][aidx] + (cc ? iR1 : iR0)
                                  + ah_[0][mt][aidx] + (cc ? hR1 : hR0));
                float Z = sigmoidf_(ai_[1][mt][aidx] + (cc ? iZ1 : iZ0)
                                  + ah_[1][mt][aidx] + (cc ? hZ1 : hZ0));
                float N = tanhf(ai_[2][mt][aidx] + (cc ? iN1 : iN0)
                              + R * (ah_[2][mt][aidx] + (cc ? hN1 : hN0)));
                float hold = g_h1f[pr][(size_t)b * Hq + hp];
                float val = (1.f - Z) * N + Z * hold;
                size_t o = (size_t)b * Hq + hp;
                g_h1f[pw][o] = val;
                __half v1, v2;
                split2h(val, v1, v2);
                g_h1t[pw][0][o] = v1;
                g_h1t[pw][1][o] = v2;
            }
        }
    }
}

// ---------------- stage C: logits + argmax + one-hot ----------------------
__global__ void __launch_bounds__(256) stepC_kernel(
    const float* __restrict__ b_fc, float* __restrict__ out, int t)
{
    __shared__ float sHL[8 * Hq];
    __shared__ float sLOG[8 * Vq];
    __shared__ int   sIDX[8];
    const int pw = 1 - (t & 1);
    const int tid = threadIdx.x;
    const int tx  = tid & 31;
    const int ty  = tid >> 5;
    const int rb  = blockIdx.x * 8;

    #pragma unroll
    for (int q = 0; q < 4; q++) {
        int f4 = tid + 256 * q;
        int r  = f4 >> 7;
        int kq = f4 & 127;
        float4 v = *reinterpret_cast<const float4*>(
            &g_h1f[pw][(size_t)(rb + r) * Hq + 4 * kq]);
        *reinterpret_cast<float4*>(&sHL[r * Hq + 4 * kq]) = v;
    }
    __syncthreads();

    float acc[8];
    #pragma unroll
    for (int r = 0; r < 8; r++) acc[r] = 0.f;
    #pragma unroll 8
    for (int k = 0; k < Hq; k++) {
        float wv = g_wfcT[k * Vq + tid];
        #pragma unroll
        for (int r = 0; r < 8; r++) acc[r] += sHL[r * Hq + k] * wv;
    }
    float bf = b_fc[tid];
    #pragma unroll
    for (int r = 0; r < 8; r++) sLOG[r * Vq + tid] = acc[r] + bf;
    __syncthreads();

    {   // warp ty reduces row ty, first-max tie-break (matches jnp.argmax)
        int row = ty;
        float bv = -3.4e38f;
        int   bi = 0;
        #pragma unroll
        for (int m = 0; m < 8; m++) {
            int idx = tx + 32 * m;
            float v = sLOG[row * Vq + idx];
            if (v > bv) { bv = v; bi = idx; }
        }
        #pragma unroll
        for (int off = 16; off > 0; off >>= 1) {
            float ov = __shfl_down_sync(0xffffffffu, bv, off);
            int   oi = __shfl_down_sync(0xffffffffu, bi, off);
            if (ov > bv || (ov == bv && oi < bi)) { bv = ov; bi = oi; }
        }
        if (tx == 0) sIDX[row] = bi;
    }
    __syncthreads();
    #pragma unroll
    for (int r = 0; r < 8; r++) {
        out[(size_t)(rb + r) * (Tq * Vq) + t * Vq + tid] =
            (tid == sIDX[r]) ? 1.0f : 0.0f;
    }
    if (tid < 8) g_idx[rb + tid] = sIDX[tid];
}

// ---------------- launch ---------------------------------------------------
extern "C" void kernel_launch(void* const* d_in, const int* in_sizes, int n_in,
                              void* d_out, int out_size)
{
    const float* latent = (const float*)d_in[0];
    // d_in[1] enthalpy: unused on freerun path
    const float* w_ih0  = (const float*)d_in[2];
    const float* w_hh0  = (const float*)d_in[3];
    const float* b_ih0  = (const float*)d_in[4];
    const float* b_hh0  = (const float*)d_in[5];
    const float* w_ih1  = (const float*)d_in[6];
    const float* w_hh1  = (const float*)d_in[7];
    const float* b_ih1  = (const float*)d_in[8];
    const float* b_hh1  = (const float*)d_in[9];
    const float* w_fc   = (const float*)d_in[10];
    const float* b_fc   = (const float*)d_in[11];
    float* out = (float*)d_out;

    init_kernel<<<128, 256>>>(latent, w_ih0, w_fc, w_hh0, w_ih1, w_hh1);
    pre_kernel<<<256, 256>>>(b_ih0);
    for (int t = 0; t < Tq; t++) {
        stepA_kernel<<<256, 256>>>(b_hh0, t);
        stepB_kernel<<<256, 256>>>(b_ih1, b_hh1, t);
        stepC_kernel<<<128, 256>>>(b_fc, out, t);
    }
}